// round 14
// baseline (speedup 1.0000x reference)
#include <cuda_runtime.h>
#include <cuda_bf16.h>
#include <cuda_fp16.h>
#include <cstdint>

#define NN 50000
#define NE 600000
#define NG 500
#define D 128
#define DOUT 32
#define WTERM 16384      // 128*128
#define WSZ (3*WTERM)    // per-layer folded terms

// ---------------- scratch ----------------
__device__ int   g_is64;
__device__ int   d_degi[NN];
__device__ float d_dinv[NN];
__device__ int   d_cnt[NN];
__device__ int   d_rowptr[NN + 1];
__device__ int   d_cursor[NN];
__device__ int   d_csr_src[NE];
__device__ float d_csr_w[NE];
__device__ int   d_batch[NN];
__device__ uint2 d_h16a[(size_t)NN * 32];   // fp16 X / layer output
__device__ uint2 d_h16b[(size_t)NN * 32];   // fp16 Tx1
__device__ uint2 d_h16c[(size_t)NN * 32];   // fp16 Tx2
__device__ __half d_W16[3 * WSZ];           // folded fp16 weights

// ---------------- zero + dtype detect ----------------
__global__ void zero_kernel(const int* __restrict__ ei_raw) {
    int i = blockIdx.x * blockDim.x + threadIdx.x;
    if (i < NN) { d_degi[i] = 0; d_cnt[i] = 0; }
    if (blockIdx.x == 0 && threadIdx.x < 32) {
        int nz = 0;
        for (int j = threadIdx.x; j < 2048; j += 32)
            if (j & 1) nz += (ei_raw[j] != 0);
        for (int off = 16; off > 0; off >>= 1)
            nz += __shfl_down_sync(0xFFFFFFFFu, nz, off);
        if (threadIdx.x == 0) g_is64 = (nz == 0) ? 1 : 0;
    }
}

// ---------------- degree histograms + batch convert (reads edge_index directly) ----------------
__global__ void convert_kernel(const void* __restrict__ ei, const void* __restrict__ batch) {
    int e = blockIdx.x * blockDim.x + threadIdx.x;
    const bool is64 = (g_is64 != 0);
    if (e < NE) {
        int s, d;
        if (is64) {
            s = (int)((const long long*)ei)[e];
            d = (int)((const long long*)ei)[(size_t)NE + e];
        } else {
            s = ((const int*)ei)[e];
            d = ((const int*)ei)[NE + e];
        }
        atomicAdd(&d_degi[s], 1);
        atomicAdd(&d_cnt[d], 1);
    }
    if (e < NN) {
        d_batch[e] = is64 ? (int)((const long long*)batch)[e] : ((const int*)batch)[e];
    }
}

// ---------------- single-block scan (+ fused dinv); 1024 thr x 49 elems ----------------
__global__ void scan_kernel() {
    __shared__ int ssum[1024];
    const int t = threadIdx.x;
    const int base = t * 49;
    int s = 0;
#pragma unroll 7
    for (int j = 0; j < 49; ++j) {
        int i = base + j;
        if (i < NN) s += d_cnt[i];
    }
    ssum[t] = s;
    __syncthreads();
    for (int off = 1; off < 1024; off <<= 1) {
        int v = (t >= off) ? ssum[t - off] : 0;
        __syncthreads();
        ssum[t] += v;
        __syncthreads();
    }
    int run = ssum[t] - s;
    for (int j = 0; j < 49; ++j) {
        int i = base + j;
        if (i < NN) {
            int c = d_cnt[i];
            d_rowptr[i] = run;
            d_cursor[i] = run;
            run += c;
            int dg = d_degi[i];
            d_dinv[i] = (dg > 0) ? rsqrtf((float)dg) : 0.0f;
        }
    }
    if (t == 0) d_rowptr[NN] = NE;
}

// ---------------- scatter: reads edge_index directly; scalar CSR outputs ----------------
__global__ void scatter_kernel(const void* __restrict__ ei) {
    int e = blockIdx.x * blockDim.x + threadIdx.x;
    const bool is64 = (g_is64 != 0);
    if (e < NE) {
        int s, d;
        if (is64) {
            s = (int)((const long long*)ei)[e];
            d = (int)((const long long*)ei)[(size_t)NE + e];
        } else {
            s = ((const int*)ei)[e];
            d = ((const int*)ei)[NE + e];
        }
        int p = atomicAdd(&d_cursor[d], 1);
        d_csr_src[p] = s;
        d_csr_w[p] = -(d_dinv[s] * d_dinv[d]);
    }
}

// ---------------- folded weights: Wa=W0-W2, Wb=W1, Wc=2*W2 -> fp16 ----------------
__global__ void wconv_kernel(const float* __restrict__ W1, const float* __restrict__ W2,
                             const float* __restrict__ W3) {
    int i = blockIdx.x * blockDim.x + threadIdx.x;
    if (i >= WTERM) return;
    const float* Ws[3] = {W1, W2, W3};
#pragma unroll
    for (int l = 0; l < 3; ++l) {
        float w0 = Ws[l][i];
        float w1 = Ws[l][WTERM + i];
        float w2 = Ws[l][2 * WTERM + i];
        int base = l * WSZ;
        d_W16[base + i] = __float2half_rn(w0 - w2);
        d_W16[base + WTERM + i] = __float2half_rn(w1);
        d_W16[base + 2 * WTERM + i] = __float2half_rn(2.0f * w2);
    }
}

// ---------------- x -> fp16 copy ----------------
__global__ void xconv_kernel(const float4* __restrict__ x) {
    int i = blockIdx.x * blockDim.x + threadIdx.x;
    if (i >= NN * 32) return;
    float4 v = x[i];
    __half2 a = __floats2half2_rn(v.x, v.y);
    __half2 b = __floats2half2_rn(v.z, v.w);
    uint2 p;
    p.x = *reinterpret_cast<uint32_t*>(&a);
    p.y = *reinterpret_cast<uint32_t*>(&b);
    d_h16a[i] = p;
}

// ---------------- lhat: R4/R10 exact — warp per row, unpredicated 8-batch ----------------
__global__ void lhat_kernel(const uint2* __restrict__ in, uint2* __restrict__ out16) {
    int w = (blockIdx.x * blockDim.x + threadIdx.x) >> 5;
    int lane = threadIdx.x & 31;
    if (w >= NN) return;
    int e = d_rowptr[w];
    const int e1 = d_rowptr[w + 1];
    float4 acc = make_float4(0.f, 0.f, 0.f, 0.f);
    for (; e + 8 <= e1; e += 8) {
        int   si[8];
        float wi[8];
        uint2 pi[8];
#pragma unroll
        for (int j = 0; j < 8; ++j) { si[j] = d_csr_src[e + j]; wi[j] = d_csr_w[e + j]; }
#pragma unroll
        for (int j = 0; j < 8; ++j) pi[j] = in[(size_t)si[j] * 32 + lane];
#pragma unroll
        for (int j = 0; j < 8; ++j) {
            float2 f0 = __half22float2(*reinterpret_cast<__half2*>(&pi[j].x));
            float2 f1 = __half22float2(*reinterpret_cast<__half2*>(&pi[j].y));
            acc.x += wi[j] * f0.x; acc.y += wi[j] * f0.y;
            acc.z += wi[j] * f1.x; acc.w += wi[j] * f1.y;
        }
    }
    {
        int rem = e1 - e;
        int   si[7];
        float wi[7];
        uint2 pi[7];
#pragma unroll
        for (int j = 0; j < 7; ++j)
            if (j < rem) { si[j] = d_csr_src[e + j]; wi[j] = d_csr_w[e + j]; }
#pragma unroll
        for (int j = 0; j < 7; ++j)
            if (j < rem) pi[j] = in[(size_t)si[j] * 32 + lane];
#pragma unroll
        for (int j = 0; j < 7; ++j)
            if (j < rem) {
                float2 f0 = __half22float2(*reinterpret_cast<__half2*>(&pi[j].x));
                float2 f1 = __half22float2(*reinterpret_cast<__half2*>(&pi[j].y));
                acc.x += wi[j] * f0.x; acc.y += wi[j] * f0.y;
                acc.z += wi[j] * f1.x; acc.w += wi[j] * f1.y;
            }
    }
    __half2 a = __floats2half2_rn(acc.x, acc.y);
    __half2 b = __floats2half2_rn(acc.z, acc.w);
    uint2 p;
    p.x = *reinterpret_cast<uint32_t*>(&a);
    p.y = *reinterpret_cast<uint32_t*>(&b);
    out16[(size_t)w * 32 + lane] = p;
}

// ---------------- tensor-core helpers ----------------
__device__ __forceinline__ void ldsm4(uint32_t a, uint32_t& r0, uint32_t& r1,
                                      uint32_t& r2, uint32_t& r3) {
    asm volatile("ldmatrix.sync.aligned.m8n8.x4.shared.b16 {%0,%1,%2,%3}, [%4];"
                 : "=r"(r0), "=r"(r1), "=r"(r2), "=r"(r3) : "r"(a));
}
__device__ __forceinline__ void ldsm4t(uint32_t a, uint32_t& r0, uint32_t& r1,
                                       uint32_t& r2, uint32_t& r3) {
    asm volatile("ldmatrix.sync.aligned.m8n8.x4.trans.shared.b16 {%0,%1,%2,%3}, [%4];"
                 : "=r"(r0), "=r"(r1), "=r"(r2), "=r"(r3) : "r"(a));
}
__device__ __forceinline__ void mma16816h(float* c, const uint32_t* a, const uint32_t* b) {
    asm volatile(
        "mma.sync.aligned.m16n8k16.row.col.f32.f16.f16.f32 "
        "{%0,%1,%2,%3}, {%4,%5,%6,%7}, {%8,%9}, {%0,%1,%2,%3};"
        : "+f"(c[0]), "+f"(c[1]), "+f"(c[2]), "+f"(c[3])
        : "r"(a[0]), "r"(a[1]), "r"(a[2]), "r"(a[3]), "r"(b[0]), "r"(b[1]));
}
__device__ __forceinline__ void cpasync16(uint32_t smem, const void* gmem) {
    asm volatile("cp.async.cg.shared.global [%0], [%1], 16;\n"
                 :: "r"(smem), "l"(gmem) : "memory");
}

// ---------------- Out16 = relu(X0@Wa + X1@Wb + X2@Wc + b); cp.async double-buffered ----------------
__global__ void __launch_bounds__(256) gemm3_kernel(
    const uint4* __restrict__ X0, const uint4* __restrict__ X1,
    const uint4* __restrict__ X2, const __half* __restrict__ W16,
    const float* __restrict__ bias, uint32_t* __restrict__ Outh)
{
    __shared__ __align__(16) unsigned char sA[2][128 * 48];  // 128 rows x 16 fp16 (+pad)
    __shared__ __align__(16) unsigned char sB[2][16 * 272];  // 16 k x 128 fp16 (+pad)
    __shared__ float s_bias[128];

    const int tid = threadIdx.x;
    const int lane = tid & 31;
    const int wid = tid >> 5;
    const int wr = wid >> 2;
    const int wc = wid & 3;
    const int m0 = blockIdx.x * 128;

    if (tid < 128) s_bias[tid] = bias[tid];

    float acc[4][4][4];
#pragma unroll
    for (int f = 0; f < 4; ++f)
#pragma unroll
        for (int t = 0; t < 4; ++t)
#pragma unroll
            for (int i = 0; i < 4; ++i) acc[f][t][i] = 0.f;

    const uint32_t sAB0 = (uint32_t)__cvta_generic_to_shared(sA[0]);
    const uint32_t sAB1 = (uint32_t)__cvta_generic_to_shared(sA[1]);
    const uint32_t sBB0 = (uint32_t)__cvta_generic_to_shared(sB[0]);
    const uint32_t sBB1 = (uint32_t)__cvta_generic_to_shared(sB[1]);
    const uint32_t aoff = (uint32_t)(lane & 15) * 48 + (uint32_t)(lane >> 4) * 16;
    const uint32_t boff = (uint32_t)(lane & 15) * 272 + (uint32_t)((lane >> 4) * 8) * 2;

    const int arow = tid >> 1;      // 0..127
    const int ahalf = tid & 1;      // 16B half of 32B row chunk
    const int brow = tid >> 4;      // 0..15
    const int bc = tid & 15;        // 16B group

    // Clamp out-of-range rows to NN-1: finite garbage, never written back.
    const int marow = (m0 + arow < NN) ? (m0 + arow) : (NN - 1);
    const uint32_t sa_dst0 = sAB0 + (uint32_t)(arow * 48 + ahalf * 16);
    const uint32_t sa_dst1 = sAB1 + (uint32_t)(arow * 48 + ahalf * 16);
    const uint32_t sb_dst0 = sBB0 + (uint32_t)(brow * 272 + bc * 16);
    const uint32_t sb_dst1 = sBB1 + (uint32_t)(brow * 272 + bc * 16);

    const uint4* Xs[3] = {X0, X1, X2};
    const uint4* Wb = (const uint4*)W16;

    // stage iteration it = sel*8 + kb  (24 total)
    // One layer-term weight block = 128*128 fp16 = 32768 B = 2048 uint4.
    auto stage = [&](int it, int buf) {
        int sel = it >> 3, kb = it & 7;
        const uint4* X = Xs[sel];
        cpasync16(buf ? sa_dst1 : sa_dst0, &X[(size_t)marow * 16 + kb * 2 + ahalf]);
        cpasync16(buf ? sb_dst1 : sb_dst0,
                  &Wb[(size_t)sel * 2048 + (size_t)(kb * 16 + brow) * 16 + bc]);
        asm volatile("cp.async.commit_group;\n" ::: "memory");
    };

    stage(0, 0);

    for (int it = 0; it < 24; ++it) {
        const int buf = it & 1;
        if (it + 1 < 24) stage(it + 1, buf ^ 1);
        if (it + 1 < 24)
            asm volatile("cp.async.wait_group 1;\n" ::: "memory");
        else
            asm volatile("cp.async.wait_group 0;\n" ::: "memory");
        __syncthreads();

        const uint32_t sABc = buf ? sAB1 : sAB0;
        const uint32_t sBBc = buf ? sBB1 : sBB0;
        uint32_t a[4][4], b[4][2];
#pragma unroll
        for (int f = 0; f < 4; ++f) {
            uint32_t rb = (uint32_t)(wr * 64 + f * 16) * 48 + aoff;
            ldsm4(sABc + rb, a[f][0], a[f][1], a[f][2], a[f][3]);
        }
#pragma unroll
        for (int nb = 0; nb < 2; ++nb) {
            uint32_t cb = boff + (uint32_t)(wc * 32 + nb * 16) * 2;
            uint32_t r0, r1, r2, r3;
            ldsm4t(sBBc + cb, r0, r1, r2, r3);
            b[nb * 2][0] = r0; b[nb * 2][1] = r1;
            b[nb * 2 + 1][0] = r2; b[nb * 2 + 1][1] = r3;
        }
#pragma unroll
        for (int f = 0; f < 4; ++f)
#pragma unroll
            for (int t = 0; t < 4; ++t)
                mma16816h(acc[f][t], a[f], b[t]);
        __syncthreads();
    }

#pragma unroll
    for (int f = 0; f < 4; ++f) {
        int r0 = m0 + wr * 64 + f * 16 + (lane >> 2);
        int r1 = r0 + 8;
#pragma unroll
        for (int t = 0; t < 4; ++t) {
            int cb = wc * 32 + t * 8 + (lane & 3) * 2;
            if (r0 < NN) {
                float ox = fmaxf(acc[f][t][0] + s_bias[cb], 0.f);
                float oy = fmaxf(acc[f][t][1] + s_bias[cb + 1], 0.f);
                __half2 h = __floats2half2_rn(ox, oy);
                Outh[(size_t)r0 * 64 + (cb >> 1)] = *reinterpret_cast<uint32_t*>(&h);
            }
            if (r1 < NN) {
                float ox = fmaxf(acc[f][t][2] + s_bias[cb], 0.f);
                float oy = fmaxf(acc[f][t][3] + s_bias[cb + 1], 0.f);
                __half2 h = __floats2half2_rn(ox, oy);
                Outh[(size_t)r1 * 64 + (cb >> 1)] = *reinterpret_cast<uint32_t*>(&h);
            }
        }
    }
}

// ---------------- fused mean-pool (fp16 in, fp32 acc) + output projection ----------------
__global__ void poolfinal_kernel(const __half* __restrict__ H, const float* __restrict__ Wout,
                                 const float* __restrict__ bout, float* __restrict__ out) {
    int g = blockIdx.x;
    int t = threadIdx.x;  // 128
    __shared__ float sp[128];
    int lo = 0, hi = NN;
    while (lo < hi) { int m = (lo + hi) >> 1; if (d_batch[m] < g) lo = m + 1; else hi = m; }
    int s = lo;
    lo = 0; hi = NN;
    while (lo < hi) { int m = (lo + hi) >> 1; if (d_batch[m] < g + 1) lo = m + 1; else hi = m; }
    int e = lo;
    float acc = 0.f;
    for (int n = s; n < e; ++n) acc += __half2float(H[(size_t)n * D + t]);
    sp[t] = acc / fmaxf((float)(e - s), 1.0f);
    __syncthreads();
    if (t < DOUT) {
        float a = 0.f;
#pragma unroll 8
        for (int i = 0; i < D; ++i) a += sp[i] * Wout[i * DOUT + t];
        out[g * DOUT + t] = bout[t] + a;
    }
}

// ---------------- launch ----------------
extern "C" void kernel_launch(void* const* d_in, const int* in_sizes, int n_in,
                              void* d_out, int out_size) {
    const float* x     = (const float*)d_in[0];
    const void*  ei    = d_in[1];
    const void*  batch = d_in[2];
    const float* W1    = (const float*)d_in[3];
    const float* b1    = (const float*)d_in[4];
    const float* W2    = (const float*)d_in[5];
    const float* b2    = (const float*)d_in[6];
    const float* W3    = (const float*)d_in[7];
    const float* b3    = (const float*)d_in[8];
    const float* Wout  = (const float*)d_in[9];
    const float* bout  = (const float*)d_in[10];
    float* out = (float*)d_out;

    uint2 *Ha, *Hb, *Hc;
    __half *W16;
    cudaGetSymbolAddress((void**)&Ha, d_h16a);
    cudaGetSymbolAddress((void**)&Hb, d_h16b);
    cudaGetSymbolAddress((void**)&Hc, d_h16c);
    cudaGetSymbolAddress((void**)&W16, d_W16);

    const int T = 256;
    const int gE = (NE + T - 1) / T;
    const int gN = (NN + T - 1) / T;
    const int gW = (NN * 32 + T - 1) / T;
    const int gM = (NN + 127) / 128;

    zero_kernel<<<gN, T>>>((const int*)ei);
    convert_kernel<<<gE, T>>>(ei, batch);
    scan_kernel<<<1, 1024>>>();
    scatter_kernel<<<gE, T>>>(ei);
    wconv_kernel<<<(WTERM + T - 1) / T, T>>>(W1, W2, W3);
    xconv_kernel<<<gW, T>>>((const float4*)x);

    // Layer 1
    lhat_kernel<<<gW, T>>>(Ha, Hb);
    lhat_kernel<<<gW, T>>>(Hb, Hc);
    gemm3_kernel<<<gM, 256>>>((const uint4*)Ha, (const uint4*)Hb, (const uint4*)Hc,
                              W16, b1, (uint32_t*)Ha);
    // Layer 2
    lhat_kernel<<<gW, T>>>(Ha, Hb);
    lhat_kernel<<<gW, T>>>(Hb, Hc);
    gemm3_kernel<<<gM, 256>>>((const uint4*)Ha, (const uint4*)Hb, (const uint4*)Hc,
                              W16 + WSZ, b2, (uint32_t*)Ha);
    // Layer 3
    lhat_kernel<<<gW, T>>>(Ha, Hb);
    lhat_kernel<<<gW, T>>>(Hb, Hc);
    gemm3_kernel<<<gM, 256>>>((const uint4*)Ha, (const uint4*)Hb, (const uint4*)Hc,
                              W16 + 2 * WSZ, b3, (uint32_t*)Ha);

    poolfinal_kernel<<<NG, 128>>>((const __half*)Ha, Wout, bout, out);
}

// round 15
// speedup vs baseline: 1.4673x; 1.4673x over previous
#include <cuda_runtime.h>
#include <cuda_bf16.h>
#include <cuda_fp16.h>
#include <cstdint>

#define NN 50000
#define NE 600000
#define NG 500
#define D 128
#define DOUT 32
#define NCHUNK 196       // ceil(NN/256)
#define WTERM 16384      // 128*128
#define WSZ (3*WTERM)    // per-layer folded terms

// ---------------- scratch ----------------
__device__ int   g_is64;
__device__ int   d_degi[NN];
__device__ float d_dinv[NN];
__device__ int   d_cnt[NN];
__device__ int   d_rowptr[NN + 1];
__device__ int   d_cursor[NN];
__device__ int   d_bsum[256];
__device__ int   d_boff[256];
__device__ int   d_csr_src[NE];
__device__ float d_csr_w[NE];
__device__ int   d_batch[NN];
__device__ uint2 d_h16a[(size_t)NN * 32];   // fp16 X / layer output
__device__ uint2 d_h16b[(size_t)NN * 32];   // fp16 Tx1
__device__ uint2 d_h16c[(size_t)NN * 32];   // fp16 Tx2
__device__ __half d_W16[3 * WSZ];           // folded fp16 weights

// ---------------- zero + dtype detect ----------------
__global__ void zero_kernel(const int* __restrict__ ei_raw) {
    int i = blockIdx.x * blockDim.x + threadIdx.x;
    if (i < NN) { d_degi[i] = 0; d_cnt[i] = 0; }
    if (blockIdx.x == 0 && threadIdx.x < 32) {
        int nz = 0;
        for (int j = threadIdx.x; j < 2048; j += 32)
            if (j & 1) nz += (ei_raw[j] != 0);
        for (int off = 16; off > 0; off >>= 1)
            nz += __shfl_down_sync(0xFFFFFFFFu, nz, off);
        if (threadIdx.x == 0) g_is64 = (nz == 0) ? 1 : 0;
    }
}

// ---------------- degree histograms + batch convert (reads edge_index directly) ----------------
__global__ void convert_kernel(const void* __restrict__ ei, const void* __restrict__ batch) {
    int e = blockIdx.x * blockDim.x + threadIdx.x;
    const bool is64 = (g_is64 != 0);
    if (e < NE) {
        int s, d;
        if (is64) {
            s = (int)((const long long*)ei)[e];
            d = (int)((const long long*)ei)[(size_t)NE + e];
        } else {
            s = ((const int*)ei)[e];
            d = ((const int*)ei)[NE + e];
        }
        atomicAdd(&d_degi[s], 1);
        atomicAdd(&d_cnt[d], 1);
    }
    if (e < NN) {
        d_batch[e] = is64 ? (int)((const long long*)batch)[e] : ((const int*)batch)[e];
    }
}

// ---------------- 3-pass coalesced scan (pass 1 fused with dinv) ----------------
__global__ void scan1_kernel() {
    __shared__ int s[256];
    int tid = threadIdx.x;
    int i = blockIdx.x * 256 + tid;
    if (i < NN) {
        int dg = d_degi[i];
        d_dinv[i] = (dg > 0) ? rsqrtf((float)dg) : 0.0f;
    }
    int v = (i < NN) ? d_cnt[i] : 0;
    s[tid] = v;
    __syncthreads();
    for (int off = 1; off < 256; off <<= 1) {
        int t = (tid >= off) ? s[tid - off] : 0;
        __syncthreads();
        s[tid] += t;
        __syncthreads();
    }
    int incl = s[tid];
    if (i < NN) d_rowptr[i] = incl - v;
    if (tid == 255) d_bsum[blockIdx.x] = incl;
}

__global__ void scan2_kernel() {
    __shared__ int s[256];
    int tid = threadIdx.x;
    int v = (tid < NCHUNK) ? d_bsum[tid] : 0;
    s[tid] = v;
    __syncthreads();
    for (int off = 1; off < 256; off <<= 1) {
        int t = (tid >= off) ? s[tid - off] : 0;
        __syncthreads();
        s[tid] += t;
        __syncthreads();
    }
    d_boff[tid] = s[tid] - v;
}

__global__ void scan3_kernel() {
    int i = blockIdx.x * blockDim.x + threadIdx.x;
    if (i < NN) {
        int r = d_rowptr[i] + d_boff[i >> 8];
        d_rowptr[i] = r;
        d_cursor[i] = r;
    }
    if (i == NN) d_rowptr[NN] = NE;
}

// ---------------- scatter: reads edge_index directly; scalar CSR outputs ----------------
__global__ void scatter_kernel(const void* __restrict__ ei) {
    int e = blockIdx.x * blockDim.x + threadIdx.x;
    const bool is64 = (g_is64 != 0);
    if (e < NE) {
        int s, d;
        if (is64) {
            s = (int)((const long long*)ei)[e];
            d = (int)((const long long*)ei)[(size_t)NE + e];
        } else {
            s = ((const int*)ei)[e];
            d = ((const int*)ei)[NE + e];
        }
        int p = atomicAdd(&d_cursor[d], 1);
        d_csr_src[p] = s;
        d_csr_w[p] = -(d_dinv[s] * d_dinv[d]);
    }
}

// ---------------- folded weights: Wa=W0-W2, Wb=W1, Wc=2*W2 -> fp16 ----------------
__global__ void wconv_kernel(const float* __restrict__ W1, const float* __restrict__ W2,
                             const float* __restrict__ W3) {
    int i = blockIdx.x * blockDim.x + threadIdx.x;
    if (i >= WTERM) return;
    const float* Ws[3] = {W1, W2, W3};
#pragma unroll
    for (int l = 0; l < 3; ++l) {
        float w0 = Ws[l][i];
        float w1 = Ws[l][WTERM + i];
        float w2 = Ws[l][2 * WTERM + i];
        int base = l * WSZ;
        d_W16[base + i] = __float2half_rn(w0 - w2);
        d_W16[base + WTERM + i] = __float2half_rn(w1);
        d_W16[base + 2 * WTERM + i] = __float2half_rn(2.0f * w2);
    }
}

// ---------------- x -> fp16 copy ----------------
__global__ void xconv_kernel(const float4* __restrict__ x) {
    int i = blockIdx.x * blockDim.x + threadIdx.x;
    if (i >= NN * 32) return;
    float4 v = x[i];
    __half2 a = __floats2half2_rn(v.x, v.y);
    __half2 b = __floats2half2_rn(v.z, v.w);
    uint2 p;
    p.x = *reinterpret_cast<uint32_t*>(&a);
    p.y = *reinterpret_cast<uint32_t*>(&b);
    d_h16a[i] = p;
}

// ---------------- lhat: R4/R10/R13 exact — warp per row, unpredicated 8-batch ----------------
__global__ void lhat_kernel(const uint2* __restrict__ in, uint2* __restrict__ out16) {
    int w = (blockIdx.x * blockDim.x + threadIdx.x) >> 5;
    int lane = threadIdx.x & 31;
    if (w >= NN) return;
    int e = d_rowptr[w];
    const int e1 = d_rowptr[w + 1];
    float4 acc = make_float4(0.f, 0.f, 0.f, 0.f);
    for (; e + 8 <= e1; e += 8) {
        int   si[8];
        float wi[8];
        uint2 pi[8];
#pragma unroll
        for (int j = 0; j < 8; ++j) { si[j] = d_csr_src[e + j]; wi[j] = d_csr_w[e + j]; }
#pragma unroll
        for (int j = 0; j < 8; ++j) pi[j] = in[(size_t)si[j] * 32 + lane];
#pragma unroll
        for (int j = 0; j < 8; ++j) {
            float2 f0 = __half22float2(*reinterpret_cast<__half2*>(&pi[j].x));
            float2 f1 = __half22float2(*reinterpret_cast<__half2*>(&pi[j].y));
            acc.x += wi[j] * f0.x; acc.y += wi[j] * f0.y;
            acc.z += wi[j] * f1.x; acc.w += wi[j] * f1.y;
        }
    }
    {
        int rem = e1 - e;
        int   si[7];
        float wi[7];
        uint2 pi[7];
#pragma unroll
        for (int j = 0; j < 7; ++j)
            if (j < rem) { si[j] = d_csr_src[e + j]; wi[j] = d_csr_w[e + j]; }
#pragma unroll
        for (int j = 0; j < 7; ++j)
            if (j < rem) pi[j] = in[(size_t)si[j] * 32 + lane];
#pragma unroll
        for (int j = 0; j < 7; ++j)
            if (j < rem) {
                float2 f0 = __half22float2(*reinterpret_cast<__half2*>(&pi[j].x));
                float2 f1 = __half22float2(*reinterpret_cast<__half2*>(&pi[j].y));
                acc.x += wi[j] * f0.x; acc.y += wi[j] * f0.y;
                acc.z += wi[j] * f1.x; acc.w += wi[j] * f1.y;
            }
    }
    __half2 a = __floats2half2_rn(acc.x, acc.y);
    __half2 b = __floats2half2_rn(acc.z, acc.w);
    uint2 p;
    p.x = *reinterpret_cast<uint32_t*>(&a);
    p.y = *reinterpret_cast<uint32_t*>(&b);
    out16[(size_t)w * 32 + lane] = p;
}

// ---------------- tensor-core helpers ----------------
__device__ __forceinline__ void ldsm4(uint32_t a, uint32_t& r0, uint32_t& r1,
                                      uint32_t& r2, uint32_t& r3) {
    asm volatile("ldmatrix.sync.aligned.m8n8.x4.shared.b16 {%0,%1,%2,%3}, [%4];"
                 : "=r"(r0), "=r"(r1), "=r"(r2), "=r"(r3) : "r"(a));
}
__device__ __forceinline__ void ldsm4t(uint32_t a, uint32_t& r0, uint32_t& r1,
                                       uint32_t& r2, uint32_t& r3) {
    asm volatile("ldmatrix.sync.aligned.m8n8.x4.trans.shared.b16 {%0,%1,%2,%3}, [%4];"
                 : "=r"(r0), "=r"(r1), "=r"(r2), "=r"(r3) : "r"(a));
}
__device__ __forceinline__ void mma16816h(float* c, const uint32_t* a, const uint32_t* b) {
    asm volatile(
        "mma.sync.aligned.m16n8k16.row.col.f32.f16.f16.f32 "
        "{%0,%1,%2,%3}, {%4,%5,%6,%7}, {%8,%9}, {%0,%1,%2,%3};"
        : "+f"(c[0]), "+f"(c[1]), "+f"(c[2]), "+f"(c[3])
        : "r"(a[0]), "r"(a[1]), "r"(a[2]), "r"(a[3]), "r"(b[0]), "r"(b[1]));
}
__device__ __forceinline__ void cpasync16(uint32_t smem, const void* gmem) {
    asm volatile("cp.async.cg.shared.global [%0], [%1], 16;\n"
                 :: "r"(smem), "l"(gmem) : "memory");
}

// ---------------- Out16 = relu(X0@Wa + X1@Wb + X2@Wc + b); cp.async double-buffered ----------------
__global__ void __launch_bounds__(256) gemm3_kernel(
    const uint4* __restrict__ X0, const uint4* __restrict__ X1,
    const uint4* __restrict__ X2, const __half* __restrict__ W16,
    const float* __restrict__ bias, uint32_t* __restrict__ Outh)
{
    __shared__ __align__(16) unsigned char sA[2][128 * 48];  // 128 rows x 16 fp16 (+pad)
    __shared__ __align__(16) unsigned char sB[2][16 * 272];  // 16 k x 128 fp16 (+pad)
    __shared__ float s_bias[128];

    const int tid = threadIdx.x;
    const int lane = tid & 31;
    const int wid = tid >> 5;
    const int wr = wid >> 2;
    const int wc = wid & 3;
    const int m0 = blockIdx.x * 128;

    if (tid < 128) s_bias[tid] = bias[tid];

    float acc[4][4][4];
#pragma unroll
    for (int f = 0; f < 4; ++f)
#pragma unroll
        for (int t = 0; t < 4; ++t)
#pragma unroll
            for (int i = 0; i < 4; ++i) acc[f][t][i] = 0.f;

    const uint32_t sAB0 = (uint32_t)__cvta_generic_to_shared(sA[0]);
    const uint32_t sAB1 = (uint32_t)__cvta_generic_to_shared(sA[1]);
    const uint32_t sBB0 = (uint32_t)__cvta_generic_to_shared(sB[0]);
    const uint32_t sBB1 = (uint32_t)__cvta_generic_to_shared(sB[1]);
    const uint32_t aoff = (uint32_t)(lane & 15) * 48 + (uint32_t)(lane >> 4) * 16;
    const uint32_t boff = (uint32_t)(lane & 15) * 272 + (uint32_t)((lane >> 4) * 8) * 2;

    const int arow = tid >> 1;      // 0..127
    const int ahalf = tid & 1;      // 16B half of 32B row chunk
    const int brow = tid >> 4;      // 0..15
    const int bc = tid & 15;        // 16B group

    // Clamp out-of-range rows to NN-1: finite garbage, never written back.
    const int marow = (m0 + arow < NN) ? (m0 + arow) : (NN - 1);
    const uint32_t sa_dst0 = sAB0 + (uint32_t)(arow * 48 + ahalf * 16);
    const uint32_t sa_dst1 = sAB1 + (uint32_t)(arow * 48 + ahalf * 16);
    const uint32_t sb_dst0 = sBB0 + (uint32_t)(brow * 272 + bc * 16);
    const uint32_t sb_dst1 = sBB1 + (uint32_t)(brow * 272 + bc * 16);

    const uint4* Xs[3] = {X0, X1, X2};
    const uint4* Wb = (const uint4*)W16;

    // stage iteration it = sel*8 + kb  (24 total)
    // One layer-term weight block = 128*128 fp16 = 32768 B = 2048 uint4.
    auto stage = [&](int it, int buf) {
        int sel = it >> 3, kb = it & 7;
        const uint4* X = Xs[sel];
        cpasync16(buf ? sa_dst1 : sa_dst0, &X[(size_t)marow * 16 + kb * 2 + ahalf]);
        cpasync16(buf ? sb_dst1 : sb_dst0,
                  &Wb[(size_t)sel * 2048 + (size_t)(kb * 16 + brow) * 16 + bc]);
        asm volatile("cp.async.commit_group;\n" ::: "memory");
    };

    stage(0, 0);

    for (int it = 0; it < 24; ++it) {
        const int buf = it & 1;
        if (it + 1 < 24) stage(it + 1, buf ^ 1);
        if (it + 1 < 24)
            asm volatile("cp.async.wait_group 1;\n" ::: "memory");
        else
            asm volatile("cp.async.wait_group 0;\n" ::: "memory");
        __syncthreads();

        const uint32_t sABc = buf ? sAB1 : sAB0;
        const uint32_t sBBc = buf ? sBB1 : sBB0;
        uint32_t a[4][4], b[4][2];
#pragma unroll
        for (int f = 0; f < 4; ++f) {
            uint32_t rb = (uint32_t)(wr * 64 + f * 16) * 48 + aoff;
            ldsm4(sABc + rb, a[f][0], a[f][1], a[f][2], a[f][3]);
        }
#pragma unroll
        for (int nb = 0; nb < 2; ++nb) {
            uint32_t cb = boff + (uint32_t)(wc * 32 + nb * 16) * 2;
            uint32_t r0, r1, r2, r3;
            ldsm4t(sBBc + cb, r0, r1, r2, r3);
            b[nb * 2][0] = r0; b[nb * 2][1] = r1;
            b[nb * 2 + 1][0] = r2; b[nb * 2 + 1][1] = r3;
        }
#pragma unroll
        for (int f = 0; f < 4; ++f)
#pragma unroll
            for (int t = 0; t < 4; ++t)
                mma16816h(acc[f][t], a[f], b[t]);
        __syncthreads();
    }

#pragma unroll
    for (int f = 0; f < 4; ++f) {
        int r0 = m0 + wr * 64 + f * 16 + (lane >> 2);
        int r1 = r0 + 8;
#pragma unroll
        for (int t = 0; t < 4; ++t) {
            int cb = wc * 32 + t * 8 + (lane & 3) * 2;
            if (r0 < NN) {
                float ox = fmaxf(acc[f][t][0] + s_bias[cb], 0.f);
                float oy = fmaxf(acc[f][t][1] + s_bias[cb + 1], 0.f);
                __half2 h = __floats2half2_rn(ox, oy);
                Outh[(size_t)r0 * 64 + (cb >> 1)] = *reinterpret_cast<uint32_t*>(&h);
            }
            if (r1 < NN) {
                float ox = fmaxf(acc[f][t][2] + s_bias[cb], 0.f);
                float oy = fmaxf(acc[f][t][3] + s_bias[cb + 1], 0.f);
                __half2 h = __floats2half2_rn(ox, oy);
                Outh[(size_t)r1 * 64 + (cb >> 1)] = *reinterpret_cast<uint32_t*>(&h);
            }
        }
    }
}

// ---------------- fused mean-pool (fp16 in, fp32 acc) + output projection ----------------
__global__ void poolfinal_kernel(const __half* __restrict__ H, const float* __restrict__ Wout,
                                 const float* __restrict__ bout, float* __restrict__ out) {
    int g = blockIdx.x;
    int t = threadIdx.x;  // 128
    __shared__ float sp[128];
    int lo = 0, hi = NN;
    while (lo < hi) { int m = (lo + hi) >> 1; if (d_batch[m] < g) lo = m + 1; else hi = m; }
    int s = lo;
    lo = 0; hi = NN;
    while (lo < hi) { int m = (lo + hi) >> 1; if (d_batch[m] < g + 1) lo = m + 1; else hi = m; }
    int e = lo;
    float acc = 0.f;
    for (int n = s; n < e; ++n) acc += __half2float(H[(size_t)n * D + t]);
    sp[t] = acc / fmaxf((float)(e - s), 1.0f);
    __syncthreads();
    if (t < DOUT) {
        float a = 0.f;
#pragma unroll 8
        for (int i = 0; i < D; ++i) a += sp[i] * Wout[i * DOUT + t];
        out[g * DOUT + t] = bout[t] + a;
    }
}

// ---------------- launch ----------------
extern "C" void kernel_launch(void* const* d_in, const int* in_sizes, int n_in,
                              void* d_out, int out_size) {
    const float* x     = (const float*)d_in[0];
    const void*  ei    = d_in[1];
    const void*  batch = d_in[2];
    const float* W1    = (const float*)d_in[3];
    const float* b1    = (const float*)d_in[4];
    const float* W2    = (const float*)d_in[5];
    const float* b2    = (const float*)d_in[6];
    const float* W3    = (const float*)d_in[7];
    const float* b3    = (const float*)d_in[8];
    const float* Wout  = (const float*)d_in[9];
    const float* bout  = (const float*)d_in[10];
    float* out = (float*)d_out;

    uint2 *Ha, *Hb, *Hc;
    __half *W16;
    cudaGetSymbolAddress((void**)&Ha, d_h16a);
    cudaGetSymbolAddress((void**)&Hb, d_h16b);
    cudaGetSymbolAddress((void**)&Hc, d_h16c);
    cudaGetSymbolAddress((void**)&W16, d_W16);

    const int T = 256;
    const int gE = (NE + T - 1) / T;
    const int gN = (NN + T - 1) / T;
    const int gW = (NN * 32 + T - 1) / T;
    const int gM = (NN + 127) / 128;

    zero_kernel<<<gN, T>>>((const int*)ei);
    convert_kernel<<<gE, T>>>(ei, batch);
    scan1_kernel<<<NCHUNK, 256>>>();
    scan2_kernel<<<1, 256>>>();
    scan3_kernel<<<gN, T>>>();
    scatter_kernel<<<gE, T>>>(ei);
    wconv_kernel<<<(WTERM + T - 1) / T, T>>>(W1, W2, W3);
    xconv_kernel<<<gW, T>>>((const float4*)x);

    // Layer 1
    lhat_kernel<<<gW, T>>>(Ha, Hb);
    lhat_kernel<<<gW, T>>>(Hb, Hc);
    gemm3_kernel<<<gM, 256>>>((const uint4*)Ha, (const uint4*)Hb, (const uint4*)Hc,
                              W16, b1, (uint32_t*)Ha);
    // Layer 2
    lhat_kernel<<<gW, T>>>(Ha, Hb);
    lhat_kernel<<<gW, T>>>(Hb, Hc);
    gemm3_kernel<<<gM, 256>>>((const uint4*)Ha, (const uint4*)Hb, (const uint4*)Hc,
                              W16 + WSZ, b2, (uint32_t*)Ha);
    // Layer 3
    lhat_kernel<<<gW, T>>>(Ha, Hb);
    lhat_kernel<<<gW, T>>>(Hb, Hc);
    gemm3_kernel<<<gM, 256>>>((const uint4*)Ha, (const uint4*)Hb, (const uint4*)Hc,
                              W16 + 2 * WSZ, b3, (uint32_t*)Ha);

    poolfinal_kernel<<<NG, 128>>>((const __half*)Ha, Wout, bout, out);
}

// round 16
// speedup vs baseline: 1.5030x; 1.0243x over previous
#include <cuda_runtime.h>
#include <cuda_bf16.h>
#include <cuda_fp16.h>
#include <cstdint>

#define NN 50000
#define NE 600000
#define NG 500
#define D 128
#define DOUT 32
#define NCHUNK 196       // ceil(NN/256)
#define WTERM 16384      // 128*128
#define WSZ (3*WTERM)    // per-layer folded terms

// ---------------- scratch ----------------
__device__ int   g_is64;
__device__ int   d_degi[NN];
__device__ float d_dinv[NN];
__device__ int   d_cnt[NN];
__device__ int   d_rowptr[NN + 1];
__device__ int   d_cursor[NN];
__device__ int   d_bsum[256];
__device__ int   d_csr_src[NE];
__device__ float d_csr_w[NE];
__device__ int   d_batch[NN];
__device__ uint2 d_h16a[(size_t)NN * 32];   // fp16 X / layer output
__device__ uint2 d_h16b[(size_t)NN * 32];   // fp16 Tx1
__device__ uint2 d_h16c[(size_t)NN * 32];   // fp16 Tx2
__device__ __half d_W16[3 * WSZ];           // folded fp16 weights

// ---------------- zero + dtype detect ----------------
__global__ void zero_kernel(const int* __restrict__ ei_raw) {
    int i = blockIdx.x * blockDim.x + threadIdx.x;
    if (i < NN) { d_degi[i] = 0; d_cnt[i] = 0; }
    if (blockIdx.x == 0 && threadIdx.x < 32) {
        int nz = 0;
        for (int j = threadIdx.x; j < 2048; j += 32)
            if (j & 1) nz += (ei_raw[j] != 0);
        for (int off = 16; off > 0; off >>= 1)
            nz += __shfl_down_sync(0xFFFFFFFFu, nz, off);
        if (threadIdx.x == 0) g_is64 = (nz == 0) ? 1 : 0;
    }
}

// ---------------- degree histograms + batch convert (reads edge_index directly) ----------------
__global__ void convert_kernel(const void* __restrict__ ei, const void* __restrict__ batch) {
    int e = blockIdx.x * blockDim.x + threadIdx.x;
    const bool is64 = (g_is64 != 0);
    if (e < NE) {
        int s, d;
        if (is64) {
            s = (int)((const long long*)ei)[e];
            d = (int)((const long long*)ei)[(size_t)NE + e];
        } else {
            s = ((const int*)ei)[e];
            d = ((const int*)ei)[NE + e];
        }
        atomicAdd(&d_degi[s], 1);
        atomicAdd(&d_cnt[d], 1);
    }
    if (e < NN) {
        d_batch[e] = is64 ? (int)((const long long*)batch)[e] : ((const int*)batch)[e];
    }
}

// ---------------- scan pass 1 (+ fused dinv) ----------------
__global__ void scan1_kernel() {
    __shared__ int s[256];
    int tid = threadIdx.x;
    int i = blockIdx.x * 256 + tid;
    if (i < NN) {
        int dg = d_degi[i];
        d_dinv[i] = (dg > 0) ? rsqrtf((float)dg) : 0.0f;
    }
    int v = (i < NN) ? d_cnt[i] : 0;
    s[tid] = v;
    __syncthreads();
    for (int off = 1; off < 256; off <<= 1) {
        int t = (tid >= off) ? s[tid - off] : 0;
        __syncthreads();
        s[tid] += t;
        __syncthreads();
    }
    int incl = s[tid];
    if (i < NN) d_rowptr[i] = incl - v;
    if (tid == 255) d_bsum[blockIdx.x] = incl;
}

// ---------------- scan pass 2+3 fused: each block computes its own chunk offset ----------------
__global__ void scan3_kernel() {
    __shared__ int s[256];
    const int tid = threadIdx.x;
    const int b = blockIdx.x;
    // tree-sum of d_bsum[0..b)
    int v = (tid < b) ? d_bsum[tid] : 0;   // b <= 195 < 256
    s[tid] = v;
    __syncthreads();
#pragma unroll
    for (int off = 128; off > 0; off >>= 1) {
        if (tid < off) s[tid] += s[tid + off];
        __syncthreads();
    }
    const int boff = s[0];
    int i = b * 256 + tid;
    if (i < NN) {
        int r = d_rowptr[i] + boff;
        d_rowptr[i] = r;
        d_cursor[i] = r;
    }
    if (i == NN) d_rowptr[NN] = NE;
}

// ---------------- scatter: reads edge_index directly; scalar CSR outputs ----------------
__global__ void scatter_kernel(const void* __restrict__ ei) {
    int e = blockIdx.x * blockDim.x + threadIdx.x;
    const bool is64 = (g_is64 != 0);
    if (e < NE) {
        int s, d;
        if (is64) {
            s = (int)((const long long*)ei)[e];
            d = (int)((const long long*)ei)[(size_t)NE + e];
        } else {
            s = ((const int*)ei)[e];
            d = ((const int*)ei)[NE + e];
        }
        int p = atomicAdd(&d_cursor[d], 1);
        d_csr_src[p] = s;
        d_csr_w[p] = -(d_dinv[s] * d_dinv[d]);
    }
}

// ---------------- prep: x -> fp16 copy + folded weights (merged) ----------------
__global__ void prep_kernel(const float4* __restrict__ x, const float* __restrict__ W1,
                            const float* __restrict__ W2, const float* __restrict__ W3) {
    int i = blockIdx.x * blockDim.x + threadIdx.x;
    if (i < NN * 32) {
        float4 v = x[i];
        __half2 a = __floats2half2_rn(v.x, v.y);
        __half2 b = __floats2half2_rn(v.z, v.w);
        uint2 p;
        p.x = *reinterpret_cast<uint32_t*>(&a);
        p.y = *reinterpret_cast<uint32_t*>(&b);
        d_h16a[i] = p;
    }
    if (i < WTERM) {
        const float* Ws[3] = {W1, W2, W3};
#pragma unroll
        for (int l = 0; l < 3; ++l) {
            float w0 = Ws[l][i];
            float w1 = Ws[l][WTERM + i];
            float w2 = Ws[l][2 * WTERM + i];
            int base = l * WSZ;
            d_W16[base + i] = __float2half_rn(w0 - w2);
            d_W16[base + WTERM + i] = __float2half_rn(w1);
            d_W16[base + 2 * WTERM + i] = __float2half_rn(2.0f * w2);
        }
    }
}

// ---------------- lhat: R4/R10/R13 exact — warp per row, unpredicated 8-batch ----------------
__global__ void lhat_kernel(const uint2* __restrict__ in, uint2* __restrict__ out16) {
    int w = (blockIdx.x * blockDim.x + threadIdx.x) >> 5;
    int lane = threadIdx.x & 31;
    if (w >= NN) return;
    int e = d_rowptr[w];
    const int e1 = d_rowptr[w + 1];
    float4 acc = make_float4(0.f, 0.f, 0.f, 0.f);
    for (; e + 8 <= e1; e += 8) {
        int   si[8];
        float wi[8];
        uint2 pi[8];
#pragma unroll
        for (int j = 0; j < 8; ++j) { si[j] = d_csr_src[e + j]; wi[j] = d_csr_w[e + j]; }
#pragma unroll
        for (int j = 0; j < 8; ++j) pi[j] = in[(size_t)si[j] * 32 + lane];
#pragma unroll
        for (int j = 0; j < 8; ++j) {
            float2 f0 = __half22float2(*reinterpret_cast<__half2*>(&pi[j].x));
            float2 f1 = __half22float2(*reinterpret_cast<__half2*>(&pi[j].y));
            acc.x += wi[j] * f0.x; acc.y += wi[j] * f0.y;
            acc.z += wi[j] * f1.x; acc.w += wi[j] * f1.y;
        }
    }
    {
        int rem = e1 - e;
        int   si[7];
        float wi[7];
        uint2 pi[7];
#pragma unroll
        for (int j = 0; j < 7; ++j)
            if (j < rem) { si[j] = d_csr_src[e + j]; wi[j] = d_csr_w[e + j]; }
#pragma unroll
        for (int j = 0; j < 7; ++j)
            if (j < rem) pi[j] = in[(size_t)si[j] * 32 + lane];
#pragma unroll
        for (int j = 0; j < 7; ++j)
            if (j < rem) {
                float2 f0 = __half22float2(*reinterpret_cast<__half2*>(&pi[j].x));
                float2 f1 = __half22float2(*reinterpret_cast<__half2*>(&pi[j].y));
                acc.x += wi[j] * f0.x; acc.y += wi[j] * f0.y;
                acc.z += wi[j] * f1.x; acc.w += wi[j] * f1.y;
            }
    }
    __half2 a = __floats2half2_rn(acc.x, acc.y);
    __half2 b = __floats2half2_rn(acc.z, acc.w);
    uint2 p;
    p.x = *reinterpret_cast<uint32_t*>(&a);
    p.y = *reinterpret_cast<uint32_t*>(&b);
    out16[(size_t)w * 32 + lane] = p;
}

// ---------------- tensor-core helpers ----------------
__device__ __forceinline__ void ldsm4(uint32_t a, uint32_t& r0, uint32_t& r1,
                                      uint32_t& r2, uint32_t& r3) {
    asm volatile("ldmatrix.sync.aligned.m8n8.x4.shared.b16 {%0,%1,%2,%3}, [%4];"
                 : "=r"(r0), "=r"(r1), "=r"(r2), "=r"(r3) : "r"(a));
}
__device__ __forceinline__ void ldsm4t(uint32_t a, uint32_t& r0, uint32_t& r1,
                                       uint32_t& r2, uint32_t& r3) {
    asm volatile("ldmatrix.sync.aligned.m8n8.x4.trans.shared.b16 {%0,%1,%2,%3}, [%4];"
                 : "=r"(r0), "=r"(r1), "=r"(r2), "=r"(r3) : "r"(a));
}
__device__ __forceinline__ void mma16816h(float* c, const uint32_t* a, const uint32_t* b) {
    asm volatile(
        "mma.sync.aligned.m16n8k16.row.col.f32.f16.f16.f32 "
        "{%0,%1,%2,%3}, {%4,%5,%6,%7}, {%8,%9}, {%0,%1,%2,%3};"
        : "+f"(c[0]), "+f"(c[1]), "+f"(c[2]), "+f"(c[3])
        : "r"(a[0]), "r"(a[1]), "r"(a[2]), "r"(a[3]), "r"(b[0]), "r"(b[1]));
}
__device__ __forceinline__ void cpasync16(uint32_t smem, const void* gmem) {
    asm volatile("cp.async.cg.shared.global [%0], [%1], 16;\n"
                 :: "r"(smem), "l"(gmem) : "memory");
}

// ---------------- Out16 = relu(X0@Wa + X1@Wb + X2@Wc + b); 3-stage cp.async pipeline ----------------
__global__ void __launch_bounds__(256) gemm3_kernel(
    const uint4* __restrict__ X0, const uint4* __restrict__ X1,
    const uint4* __restrict__ X2, const __half* __restrict__ W16,
    const float* __restrict__ bias, uint32_t* __restrict__ Outh)
{
    __shared__ __align__(16) unsigned char sA[3][128 * 48];  // 128 rows x 16 fp16 (+pad)
    __shared__ __align__(16) unsigned char sB[3][16 * 272];  // 16 k x 128 fp16 (+pad)
    __shared__ float s_bias[128];

    const int tid = threadIdx.x;
    const int lane = tid & 31;
    const int wid = tid >> 5;
    const int wr = wid >> 2;
    const int wc = wid & 3;
    const int m0 = blockIdx.x * 128;

    if (tid < 128) s_bias[tid] = bias[tid];

    float acc[4][4][4];
#pragma unroll
    for (int f = 0; f < 4; ++f)
#pragma unroll
        for (int t = 0; t < 4; ++t)
#pragma unroll
            for (int i = 0; i < 4; ++i) acc[f][t][i] = 0.f;

    const uint32_t sAB0 = (uint32_t)__cvta_generic_to_shared(sA[0]);
    const uint32_t sAB1 = (uint32_t)__cvta_generic_to_shared(sA[1]);
    const uint32_t sAB2 = (uint32_t)__cvta_generic_to_shared(sA[2]);
    const uint32_t sBB0 = (uint32_t)__cvta_generic_to_shared(sB[0]);
    const uint32_t sBB1 = (uint32_t)__cvta_generic_to_shared(sB[1]);
    const uint32_t sBB2 = (uint32_t)__cvta_generic_to_shared(sB[2]);
    const uint32_t aoff = (uint32_t)(lane & 15) * 48 + (uint32_t)(lane >> 4) * 16;
    const uint32_t boff = (uint32_t)(lane & 15) * 272 + (uint32_t)((lane >> 4) * 8) * 2;

    const int arow = tid >> 1;      // 0..127
    const int ahalf = tid & 1;      // 16B half of 32B row chunk
    const int brow = tid >> 4;      // 0..15
    const int bc = tid & 15;        // 16B group

    // Clamp out-of-range rows to NN-1: finite garbage, never written back.
    const int marow = (m0 + arow < NN) ? (m0 + arow) : (NN - 1);
    const uint32_t sa_off = (uint32_t)(arow * 48 + ahalf * 16);
    const uint32_t sb_off = (uint32_t)(brow * 272 + bc * 16);

    const uint4* Xs[3] = {X0, X1, X2};
    const uint4* Wb = (const uint4*)W16;

    // stage iteration it = sel*8 + kb (24 total); one layer-term W block = 2048 uint4.
    auto stage = [&](int it, int buf) {
        int sel = it >> 3, kb = it & 7;
        const uint4* X = Xs[sel];
        uint32_t sa = (buf == 0) ? sAB0 : (buf == 1) ? sAB1 : sAB2;
        uint32_t sb = (buf == 0) ? sBB0 : (buf == 1) ? sBB1 : sBB2;
        cpasync16(sa + sa_off, &X[(size_t)marow * 16 + kb * 2 + ahalf]);
        cpasync16(sb + sb_off, &Wb[(size_t)sel * 2048 + (size_t)(kb * 16 + brow) * 16 + bc]);
        asm volatile("cp.async.commit_group;\n" ::: "memory");
    };
    auto compute = [&](int buf) {
        const uint32_t sABc = (buf == 0) ? sAB0 : (buf == 1) ? sAB1 : sAB2;
        const uint32_t sBBc = (buf == 0) ? sBB0 : (buf == 1) ? sBB1 : sBB2;
        uint32_t a[4][4], b[4][2];
#pragma unroll
        for (int f = 0; f < 4; ++f) {
            uint32_t rb = (uint32_t)(wr * 64 + f * 16) * 48 + aoff;
            ldsm4(sABc + rb, a[f][0], a[f][1], a[f][2], a[f][3]);
        }
#pragma unroll
        for (int nb = 0; nb < 2; ++nb) {
            uint32_t cb = boff + (uint32_t)(wc * 32 + nb * 16) * 2;
            uint32_t r0, r1, r2, r3;
            ldsm4t(sBBc + cb, r0, r1, r2, r3);
            b[nb * 2][0] = r0; b[nb * 2][1] = r1;
            b[nb * 2 + 1][0] = r2; b[nb * 2 + 1][1] = r3;
        }
#pragma unroll
        for (int f = 0; f < 4; ++f)
#pragma unroll
            for (int t = 0; t < 4; ++t)
                mma16816h(acc[f][t], a[f], b[t]);
    };

    stage(0, 0);
    stage(1, 1);

#define GSTEP(IT, BUF)                                                        \
    do {                                                                      \
        if ((IT) + 2 < 24) {                                                  \
            stage((IT) + 2, ((BUF) + 2) % 3);                                 \
            asm volatile("cp.async.wait_group 2;\n" ::: "memory");            \
        } else if ((IT) + 1 < 24) {                                           \
            asm volatile("cp.async.wait_group 1;\n" ::: "memory");            \
        } else {                                                              \
            asm volatile("cp.async.wait_group 0;\n" ::: "memory");            \
        }                                                                     \
        __syncthreads();                                                      \
        compute(BUF);                                                         \
        __syncthreads();                                                      \
    } while (0)

    for (int itb = 0; itb < 24; itb += 3) {
        GSTEP(itb + 0, 0);
        GSTEP(itb + 1, 1);
        GSTEP(itb + 2, 2);
    }
#undef GSTEP

#pragma unroll
    for (int f = 0; f < 4; ++f) {
        int r0 = m0 + wr * 64 + f * 16 + (lane >> 2);
        int r1 = r0 + 8;
#pragma unroll
        for (int t = 0; t < 4; ++t) {
            int cb = wc * 32 + t * 8 + (lane & 3) * 2;
            if (r0 < NN) {
                float ox = fmaxf(acc[f][t][0] + s_bias[cb], 0.f);
                float oy = fmaxf(acc[f][t][1] + s_bias[cb + 1], 0.f);
                __half2 h = __floats2half2_rn(ox, oy);
                Outh[(size_t)r0 * 64 + (cb >> 1)] = *reinterpret_cast<uint32_t*>(&h);
            }
            if (r1 < NN) {
                float ox = fmaxf(acc[f][t][2] + s_bias[cb], 0.f);
                float oy = fmaxf(acc[f][t][3] + s_bias[cb + 1], 0.f);
                __half2 h = __floats2half2_rn(ox, oy);
                Outh[(size_t)r1 * 64 + (cb >> 1)] = *reinterpret_cast<uint32_t*>(&h);
            }
        }
    }
}

// ---------------- fused mean-pool (fp16 in, fp32 acc) + output projection ----------------
__global__ void poolfinal_kernel(const __half* __restrict__ H, const float* __restrict__ Wout,
                                 const float* __restrict__ bout, float* __restrict__ out) {
    int g = blockIdx.x;
    int t = threadIdx.x;  // 128
    __shared__ float sp[128];
    int lo = 0, hi = NN;
    while (lo < hi) { int m = (lo + hi) >> 1; if (d_batch[m] < g) lo = m + 1; else hi = m; }
    int s = lo;
    lo = 0; hi = NN;
    while (lo < hi) { int m = (lo + hi) >> 1; if (d_batch[m] < g + 1) lo = m + 1; else hi = m; }
    int e = lo;
    float acc = 0.f;
    for (int n = s; n < e; ++n) acc += __half2float(H[(size_t)n * D + t]);
    sp[t] = acc / fmaxf((float)(e - s), 1.0f);
    __syncthreads();
    if (t < DOUT) {
        float a = 0.f;
#pragma unroll 8
        for (int i = 0; i < D; ++i) a += sp[i] * Wout[i * DOUT + t];
        out[g * DOUT + t] = bout[t] + a;
    }
}

// ---------------- launch ----------------
extern "C" void kernel_launch(void* const* d_in, const int* in_sizes, int n_in,
                              void* d_out, int out_size) {
    const float* x     = (const float*)d_in[0];
    const void*  ei    = d_in[1];
    const void*  batch = d_in[2];
    const float* W1    = (const float*)d_in[3];
    const float* b1    = (const float*)d_in[4];
    const float* W2    = (const float*)d_in[5];
    const float* b2    = (const float*)d_in[6];
    const float* W3    = (const float*)d_in[7];
    const float* b3    = (const float*)d_in[8];
    const float* Wout  = (const float*)d_in[9];
    const float* bout  = (const float*)d_in[10];
    float* out = (float*)d_out;

    uint2 *Ha, *Hb, *Hc;
    __half *W16;
    cudaGetSymbolAddress((void**)&Ha, d_h16a);
    cudaGetSymbolAddress((void**)&Hb, d_h16b);
    cudaGetSymbolAddress((void**)&Hc, d_h16c);
    cudaGetSymbolAddress((void**)&W16, d_W16);

    const int T = 256;
    const int gE = (NE + T - 1) / T;
    const int gN = (NN + T - 1) / T;
    const int gW = (NN * 32 + T - 1) / T;
    const int gM = (NN + 127) / 128;

    zero_kernel<<<gN, T>>>((const int*)ei);
    convert_kernel<<<gE, T>>>(ei, batch);
    scan1_kernel<<<NCHUNK, 256>>>();
    scan3_kernel<<<NCHUNK, 256>>>();
    scatter_kernel<<<gE, T>>>(ei);
    prep_kernel<<<gW, T>>>((const float4*)x, W1, W2, W3);

    // Layer 1
    lhat_kernel<<<gW, T>>>(Ha, Hb);
    lhat_kernel<<<gW, T>>>(Hb, Hc);
    gemm3_kernel<<<gM, 256>>>((const uint4*)Ha, (const uint4*)Hb, (const uint4*)Hc,
                              W16, b1, (uint32_t*)Ha);
    // Layer 2
    lhat_kernel<<<gW, T>>>(Ha, Hb);
    lhat_kernel<<<gW, T>>>(Hb, Hc);
    gemm3_kernel<<<gM, 256>>>((const uint4*)Ha, (const uint4*)Hb, (const uint4*)Hc,
                              W16 + WSZ, b2, (uint32_t*)Ha);
    // Layer 3
    lhat_kernel<<<gW, T>>>(Ha, Hb);
    lhat_kernel<<<gW, T>>>(Hb, Hc);
    gemm3_kernel<<<gM, 256>>>((const uint4*)Ha, (const uint4*)Hb, (const uint4*)Hc,
                              W16 + 2 * WSZ, b3, (uint32_t*)Ha);

    poolfinal_kernel<<<NG, 128>>>((const __half*)Ha, Wout, bout, out);
}